// round 16
// baseline (speedup 1.0000x reference)
#include <cuda_runtime.h>
#include <cuda_fp16.h>
#include <cstdint>
#include <cstddef>

// ============================ problem constants ============================
#define CE 8
#define CK 1024
#define CN 4096
#define CM 16384

#define BM 128
#define BN 128
#define BK 64
#define NCH (CK / BK)          // 16 K-chunks
#define NT (CN / BN)           // 32 N-tiles
#define MAXMT (CM / BM + CE)   // 136 worst-case M tiles
#define STAGES 4

#define A_PITCH 144u                     // 128B data + 16B pad -> conflict-free ldmatrix
#define A_BYTES (BM * A_PITCH)           // 18432
#define B_PITCH 256u                     // BN * 2
#define B_BYTES (BK * B_PITCH)           // 16384
#define STAGE_BYTES (A_BYTES + B_BYTES)  // 34816
#define SMEM_TOTAL (STAGES * STAGE_BYTES) // 139264 (1 CTA/SM; regs force 1 anyway)

#define NX8 (CM * CK / 8)                // 2097152 vec8 elems of x
#define NW8 (CE * CK * CN / 8)           // 4194304 vec8 elems of w
#define PRE_BLOCKS (1 + (NX8 + NW8 + 1023) / 1024)

// ============================ device globals ===============================
__device__ int g_perm[CM];
__device__ int g_tile_e[MAXMT];
__device__ int g_tile_row0[MAXMT];
__device__ int g_tile_rows[MAXMT];
__device__ int g_num_mt;
__device__ __half g_xh[(size_t)CM * CK];          // 32 MB fp16 x
__device__ __half g_wh[(size_t)CE * CK * CN];     // 64 MB fp16 weights

// ============================ PTX helpers ==================================
__device__ __forceinline__ uint32_t smem_u32(const void* p) {
    uint32_t a;
    asm("{ .reg .u64 t; cvta.to.shared.u64 t, %1; cvt.u32.u64 %0, t; }"
        : "=r"(a) : "l"(p));
    return a;
}

__device__ __forceinline__ void cp16(uint32_t dst, const void* src) {
    asm volatile("cp.async.cg.shared.global [%0], [%1], 16;"
                 :: "r"(dst), "l"(src) : "memory");
}
#define CP_COMMIT() asm volatile("cp.async.commit_group;" ::: "memory")
#define CP_WAIT(n)  asm volatile("cp.async.wait_group %0;" :: "n"(n) : "memory")

__device__ __forceinline__ void ldsm_x4(uint32_t* r, uint32_t addr) {
    asm volatile("ldmatrix.sync.aligned.m8n8.x4.shared.b16 {%0,%1,%2,%3}, [%4];"
                 : "=r"(r[0]), "=r"(r[1]), "=r"(r[2]), "=r"(r[3]) : "r"(addr));
}
__device__ __forceinline__ void ldsm_x4_t(uint32_t* r, uint32_t addr) {
    asm volatile("ldmatrix.sync.aligned.m8n8.x4.trans.shared.b16 {%0,%1,%2,%3}, [%4];"
                 : "=r"(r[0]), "=r"(r[1]), "=r"(r[2]), "=r"(r[3]) : "r"(addr));
}

// fp16-accumulate MMA: 2x the fp32-accum HMMA rate. D/C are 2 regs (4 halves).
__device__ __forceinline__ void mma16816h(uint32_t* d, const uint32_t* a,
                                          uint32_t b0, uint32_t b1) {
    asm volatile(
        "mma.sync.aligned.m16n8k16.row.col.f16.f16.f16.f16 "
        "{%0,%1}, {%2,%3,%4,%5}, {%6,%7}, {%0,%1};"
        : "+r"(d[0]), "+r"(d[1])
        : "r"(a[0]), "r"(a[1]), "r"(a[2]), "r"(a[3]), "r"(b0), "r"(b1));
}

// round through fp16 so stored f32 bit-matches the reference's fp16 cast
__device__ __forceinline__ float rnd16(float v) {
    return __half2float(__float2half_rn(v));
}

// ================= fused pre-pass: sort (block 0) + convert ================
__global__ void __launch_bounds__(1024) fused_pre(const int* __restrict__ eidx,
                                                  const void* __restrict__ x,
                                                  const void* __restrict__ w) {
    if (blockIdx.x == 0) {
        __shared__ int hist[CE][1024];
        __shared__ int tot[CE];
        __shared__ int off[CE];
        int t = threadIdx.x;

        int c[CE];
#pragma unroll
        for (int e = 0; e < CE; e++) c[e] = 0;
        int base = t * 16;
#pragma unroll
        for (int i = 0; i < 16; i++) {
            int e = eidx[base + i] & 7;
#pragma unroll
            for (int q = 0; q < CE; q++) if (e == q) c[q]++;
        }
#pragma unroll
        for (int e = 0; e < CE; e++) hist[e][t] = c[e];
        __syncthreads();

        int wjd = t >> 5, l = t & 31;
        if (wjd < CE) {
            int s = 0;
            for (int i = 0; i < 32; i++) s += hist[wjd][l * 32 + i];
            int run = s;
            for (int d = 1; d < 32; d <<= 1) {
                int v = __shfl_up_sync(0xffffffffu, run, d);
                if (l >= d) run += v;
            }
            int excl = run - s;
            if (l == 31) tot[wjd] = run;
            int acc = excl;
            for (int i = 0; i < 32; i++) {
                int v = hist[wjd][l * 32 + i];
                hist[wjd][l * 32 + i] = acc;
                acc += v;
            }
        }
        __syncthreads();
        if (t == 0) {
            int a = 0;
            for (int e = 0; e < CE; e++) { off[e] = a; a += tot[e]; }
        }
        __syncthreads();

        int pos[CE];
#pragma unroll
        for (int e = 0; e < CE; e++) pos[e] = off[e] + hist[e][t];
        for (int i = 0; i < 16; i++) {
            int tok = base + i;
            int e = eidx[tok] & 7;
            g_perm[pos[e]++] = tok;
        }

        if (t == 0) {
            int nmt = 0;
            for (int e = 0; e < CE; e++) {
                int cnt = tot[e], b = off[e];
                for (int r = 0; r < cnt; r += BM) {
                    g_tile_e[nmt] = e;
                    g_tile_row0[nmt] = b + r;
                    g_tile_rows[nmt] = (cnt - r < BM) ? (cnt - r) : BM;
                    nmt++;
                }
            }
            g_num_mt = nmt;
            for (int j = nmt; j < MAXMT; j++) { g_tile_rows[j] = 0; g_tile_e[j] = 0; g_tile_row0[j] = 0; }
        }
        return;
    }

    int i = (blockIdx.x - 1) * 1024 + threadIdx.x;   // vec8 index
    const void* src; __half* dst; int idx;
    if (i < NX8) { src = x; dst = g_xh; idx = i; }
    else if (i < NX8 + NW8) { src = w; dst = g_wh; idx = i - NX8; }
    else return;

    uint4 probe = reinterpret_cast<const uint4*>(x)[0];   // broadcast, cached
    bool isf32 = ((probe.x | probe.y | probe.z | probe.w) & 0x1FFFu) == 0u;

    if (isf32) {
        const float4* sf = reinterpret_cast<const float4*>(src);
        float4 a = sf[2 * idx], b = sf[2 * idx + 1];
        __half2 h0 = __floats2half2_rn(a.x, a.y);
        __half2 h1 = __floats2half2_rn(a.z, a.w);
        __half2 h2 = __floats2half2_rn(b.x, b.y);
        __half2 h3 = __floats2half2_rn(b.z, b.w);
        uint4 o;
        o.x = *reinterpret_cast<uint32_t*>(&h0);
        o.y = *reinterpret_cast<uint32_t*>(&h1);
        o.z = *reinterpret_cast<uint32_t*>(&h2);
        o.w = *reinterpret_cast<uint32_t*>(&h3);
        reinterpret_cast<uint4*>(dst)[idx] = o;
    } else {
        reinterpret_cast<uint4*>(dst)[idx] = reinterpret_cast<const uint4*>(src)[idx];
    }
}

// ============================ grouped GEMM =================================
// 256 threads = 8 warps, warp grid 2(M)x4(N), each warp 64x32.
// fp16 accumulation WITHIN each BK=64 chunk (2x HMMA rate), promoted to fp32
// registers at chunk boundaries (error ~3e-4 << 1e-3 threshold).
// 4-stage cp.async pipeline; regs ~150 -> 1 CTA/SM.
__global__ void __launch_bounds__(256) moe_gemm(float* __restrict__ out) {
    extern __shared__ char smem[];
    const __half* __restrict__ x = g_xh;
    const __half* __restrict__ wts = g_wh;
    const int tid = threadIdx.x;
    const int lane = tid & 31;
    const int wid = tid >> 5;
    const int warp_m = wid & 1;   // 0..1
    const int warp_n = wid >> 1;  // 0..3

    const int mt = blockIdx.x >> 5;     // NT = 32
    const int nt = blockIdx.x & 31;
    if (mt >= g_num_mt) return;
    const int rows = g_tile_rows[mt];
    if (rows <= 0) return;
    const int e = g_tile_e[mt];
    const int row0 = g_tile_row0[mt];
    const int nb = nt * BN;

    const uint32_t sbase = smem_u32(smem);

    // ---- A cp.async setup: 128 rows x 8 segs(16B); thread does 4 (gathered) ----
    const int rA = tid >> 3;          // 0..31, +32*j
    const int segA = tid & 7;
    const __half* aptr[4];
    uint32_t adst[4];
#pragma unroll
    for (int j = 0; j < 4; j++) {
        int rowj = rA + 32 * j;
        int rr = (rowj < rows) ? rowj : 0;
        int tok = g_perm[row0 + rr];
        aptr[j] = x + (size_t)tok * CK + segA * 8;
        adst[j] = sbase + (uint32_t)rowj * A_PITCH + (uint32_t)segA * 16u;
    }
    // ---- B cp.async setup: 64 rows x 16 segs(16B); thread does 4, single base ----
    const int rB0 = tid >> 4;        // 0..15
    const int sB0 = tid & 15;
    const __half* bsrc = wts + ((size_t)e * CK + rB0) * CN + nb + sB0 * 8;
    const uint32_t bdst0 = sbase + A_BYTES + (uint32_t)rB0 * B_PITCH
                         + (uint32_t)((sB0 ^ (rB0 & 7)) * 16);

    // ---- pipeline ----
    auto load_stage = [&](int c2) {
        uint32_t soff = (uint32_t)(c2 % STAGES) * STAGE_BYTES;
        size_t ka = (size_t)c2 * BK;
        size_t kb = (size_t)c2 * BK * CN;
#pragma unroll
        for (int j = 0; j < 4; j++) cp16(adst[j] + soff, aptr[j] + ka);
#pragma unroll
        for (int j = 0; j < 4; j++)
            cp16(bdst0 + soff + (uint32_t)j * (16u * B_PITCH),
                 bsrc + kb + (size_t)j * 16 * CN);
        CP_COMMIT();
    };

#pragma unroll
    for (int c2 = 0; c2 < STAGES - 1; c2++) load_stage(c2);

    float acc[4][4][4];
#pragma unroll
    for (int i = 0; i < 4; i++)
#pragma unroll
        for (int j = 0; j < 4; j++)
#pragma unroll
            for (int q = 0; q < 4; q++) acc[i][j][q] = 0.0f;

    const uint32_t a_row_base = (uint32_t)(warp_m * 64 + (lane & 15));
    const uint32_t a_col16 = (uint32_t)(lane >> 4) * 16u;
    const uint32_t b_krow_lane = (uint32_t)(lane & 15);
    const uint32_t b_cseg_base = (uint32_t)(warp_n * 4 + (lane >> 4));

    for (int c2 = 0; c2 < NCH; c2++) {
        CP_WAIT(STAGES - 2);
        __syncthreads();
        // tail: always commit a group so the wait forces completion.
        if (c2 + STAGES - 1 < NCH) load_stage(c2 + STAGES - 1);
        else                       CP_COMMIT();

        uint32_t ab = sbase + (uint32_t)(c2 % STAGES) * STAGE_BYTES;
        uint32_t bb = ab + A_BYTES;

        // fp16 chunk accumulators (zeroed per chunk)
        uint32_t hacc[4][4][2];
#pragma unroll
        for (int m = 0; m < 4; m++)
#pragma unroll
            for (int j = 0; j < 4; j++) { hacc[m][j][0] = 0u; hacc[m][j][1] = 0u; }

#pragma unroll
        for (int k16 = 0; k16 < BK / 16; k16++) {
            uint32_t a[4][4];
#pragma unroll
            for (int m = 0; m < 4; m++) {
                uint32_t row = a_row_base + m * 16;
                ldsm_x4(a[m], ab + row * A_PITCH + (uint32_t)k16 * 32u + a_col16);
            }
            uint32_t bfr[2][4];
            uint32_t krow = (uint32_t)k16 * 16u + b_krow_lane;
#pragma unroll
            for (int p = 0; p < 2; p++) {
                uint32_t cseg = (b_cseg_base + p * 2) ^ (krow & 7u);
                ldsm_x4_t(bfr[p], bb + krow * B_PITCH + cseg * 16u);
            }
#pragma unroll
            for (int m = 0; m < 4; m++)
#pragma unroll
                for (int j = 0; j < 4; j++)
                    mma16816h(hacc[m][j], a[m], bfr[j >> 1][(j & 1) * 2],
                              bfr[j >> 1][(j & 1) * 2 + 1]);
        }

        // promote chunk partials to fp32
#pragma unroll
        for (int m = 0; m < 4; m++)
#pragma unroll
            for (int j = 0; j < 4; j++) {
                __half2 h0 = *reinterpret_cast<__half2*>(&hacc[m][j][0]);
                __half2 h1 = *reinterpret_cast<__half2*>(&hacc[m][j][1]);
                float2 f0 = __half22float2(h0);
                float2 f1 = __half22float2(h1);
                acc[m][j][0] += f0.x;
                acc[m][j][1] += f0.y;
                acc[m][j][2] += f1.x;
                acc[m][j][3] += f1.y;
            }
    }

    // ---- epilogue: fp32 accum -> fp16 rounding -> FLOAT32 stores ----
    const int rm_base = warp_m * 64 + (lane >> 2);
    const int cn_base = nb + warp_n * 32 + (lane & 3) * 2;
#pragma unroll
    for (int m = 0; m < 4; m++) {
        int rm0 = rm_base + m * 16;
        bool ok0 = rm0 < rows;
        bool ok1 = rm0 + 8 < rows;
        float* o0 = out + (size_t)(row0 + rm0) * CN;
        float* o1 = o0 + (size_t)8 * CN;
#pragma unroll
        for (int j = 0; j < 4; j++) {
            int cn = cn_base + (j >> 1) * 16 + (j & 1) * 8;
            if (ok0) {
                float2 v = make_float2(rnd16(acc[m][j][0]), rnd16(acc[m][j][1]));
                *reinterpret_cast<float2*>(o0 + cn) = v;
            }
            if (ok1) {
                float2 v = make_float2(rnd16(acc[m][j][2]), rnd16(acc[m][j][3]));
                *reinterpret_cast<float2*>(o1 + cn) = v;
            }
        }
    }
}

// ============================ launch =======================================
extern "C" void kernel_launch(void* const* d_in, const int* in_sizes, int n_in,
                              void* d_out, int out_size) {
    const void* x = nullptr;
    const int*  ei = nullptr;
    const void* w = nullptr;
    for (int i = 0; i < n_in; i++) {
        if (in_sizes[i] == CM * CK)            x  = d_in[i];
        else if (in_sizes[i] == CM)            ei = (const int*)d_in[i];
        else if (in_sizes[i] == CE * CK * CN)  w  = d_in[i];
    }
    float* out = (float*)d_out;

    // 2 launches/call: fused (sort + convert), gemm.
    fused_pre<<<PRE_BLOCKS, 1024>>>(ei, x, w);

    cudaFuncSetAttribute(moe_gemm, cudaFuncAttributeMaxDynamicSharedMemorySize, SMEM_TOTAL);
    moe_gemm<<<MAXMT * NT, 256, SMEM_TOTAL>>>(out);
}

// round 17
// speedup vs baseline: 1.3981x; 1.3981x over previous
#include <cuda_runtime.h>
#include <cuda_fp16.h>
#include <cstdint>
#include <cstddef>

// ============================ problem constants ============================
#define CE 8
#define CK 1024
#define CN 4096
#define CM 16384

#define BM 128
#define BN 128
#define BK 64
#define NCH (CK / BK)          // 16 K-chunks
#define NT (CN / BN)           // 32 N-tiles
#define MAXMT (CM / BM + CE)   // 136 worst-case M tiles
#define STAGES 3

#define A_PITCH 144u                     // 128B data + 16B pad -> conflict-free ldmatrix
#define A_BYTES (BM * A_PITCH)           // 18432
#define B_PITCH 256u                     // BN * 2
#define B_BYTES (BK * B_PITCH)           // 16384
#define STAGE_BYTES (A_BYTES + B_BYTES)  // 34816
#define SMEM_TOTAL (STAGES * STAGE_BYTES) // 104448 -> 2 CTAs/SM

#define NX8 (CM * CK / 8)                // 2097152 vec8 elems of x
#define NW8 (CE * CK * CN / 8)           // 4194304 vec8 elems of w
#define PRE_BLOCKS (1 + (NX8 + NW8 + 1023) / 1024)

// ============================ device globals ===============================
__device__ int g_perm[CM];
__device__ int g_tile_e[MAXMT];
__device__ int g_tile_row0[MAXMT];
__device__ int g_tile_rows[MAXMT];
__device__ int g_num_mt;
__device__ __half g_xh[(size_t)CM * CK];          // 32 MB fp16 x
__device__ __half g_wh[(size_t)CE * CK * CN];     // 64 MB fp16 weights

// ============================ PTX helpers ==================================
__device__ __forceinline__ uint32_t smem_u32(const void* p) {
    uint32_t a;
    asm("{ .reg .u64 t; cvta.to.shared.u64 t, %1; cvt.u32.u64 %0, t; }"
        : "=r"(a) : "l"(p));
    return a;
}

__device__ __forceinline__ void cp16(uint32_t dst, const void* src) {
    asm volatile("cp.async.cg.shared.global [%0], [%1], 16;"
                 :: "r"(dst), "l"(src) : "memory");
}
#define CP_COMMIT() asm volatile("cp.async.commit_group;" ::: "memory")
#define CP_WAIT(n)  asm volatile("cp.async.wait_group %0;" :: "n"(n) : "memory")

__device__ __forceinline__ void ldsm_x4(uint32_t* r, uint32_t addr) {
    asm volatile("ldmatrix.sync.aligned.m8n8.x4.shared.b16 {%0,%1,%2,%3}, [%4];"
                 : "=r"(r[0]), "=r"(r[1]), "=r"(r[2]), "=r"(r[3]) : "r"(addr));
}
__device__ __forceinline__ void ldsm_x4_t(uint32_t* r, uint32_t addr) {
    asm volatile("ldmatrix.sync.aligned.m8n8.x4.trans.shared.b16 {%0,%1,%2,%3}, [%4];"
                 : "=r"(r[0]), "=r"(r[1]), "=r"(r[2]), "=r"(r[3]) : "r"(addr));
}

__device__ __forceinline__ void mma16816(float* c, const uint32_t* a,
                                         uint32_t b0, uint32_t b1) {
    asm volatile(
        "mma.sync.aligned.m16n8k16.row.col.f32.f16.f16.f32 "
        "{%0,%1,%2,%3}, {%4,%5,%6,%7}, {%8,%9}, {%0,%1,%2,%3};"
        : "+f"(c[0]), "+f"(c[1]), "+f"(c[2]), "+f"(c[3])
        : "r"(a[0]), "r"(a[1]), "r"(a[2]), "r"(a[3]), "r"(b0), "r"(b1));
}

// round through fp16 so stored f32 bit-matches the reference's fp16 cast
__device__ __forceinline__ float rnd16(float v) {
    return __half2float(__float2half_rn(v));
}

// ================= fused pre-pass: sort (block 0) + convert ================
__global__ void __launch_bounds__(1024) fused_pre(const int* __restrict__ eidx,
                                                  const void* __restrict__ x,
                                                  const void* __restrict__ w) {
    if (blockIdx.x == 0) {
        __shared__ int hist[CE][1024];
        __shared__ int tot[CE];
        __shared__ int off[CE];
        int t = threadIdx.x;

        int c[CE];
#pragma unroll
        for (int e = 0; e < CE; e++) c[e] = 0;
        int base = t * 16;
#pragma unroll
        for (int i = 0; i < 16; i++) {
            int e = eidx[base + i] & 7;
#pragma unroll
            for (int q = 0; q < CE; q++) if (e == q) c[q]++;
        }
#pragma unroll
        for (int e = 0; e < CE; e++) hist[e][t] = c[e];
        __syncthreads();

        int wjd = t >> 5, l = t & 31;
        if (wjd < CE) {
            int s = 0;
            for (int i = 0; i < 32; i++) s += hist[wjd][l * 32 + i];
            int run = s;
            for (int d = 1; d < 32; d <<= 1) {
                int v = __shfl_up_sync(0xffffffffu, run, d);
                if (l >= d) run += v;
            }
            int excl = run - s;
            if (l == 31) tot[wjd] = run;
            int acc = excl;
            for (int i = 0; i < 32; i++) {
                int v = hist[wjd][l * 32 + i];
                hist[wjd][l * 32 + i] = acc;
                acc += v;
            }
        }
        __syncthreads();
        if (t == 0) {
            int a = 0;
            for (int e = 0; e < CE; e++) { off[e] = a; a += tot[e]; }
        }
        __syncthreads();

        int pos[CE];
#pragma unroll
        for (int e = 0; e < CE; e++) pos[e] = off[e] + hist[e][t];
        for (int i = 0; i < 16; i++) {
            int tok = base + i;
            int e = eidx[tok] & 7;
            g_perm[pos[e]++] = tok;
        }

        if (t == 0) {
            int nmt = 0;
            for (int e = 0; e < CE; e++) {
                int cnt = tot[e], b = off[e];
                for (int r = 0; r < cnt; r += BM) {
                    g_tile_e[nmt] = e;
                    g_tile_row0[nmt] = b + r;
                    g_tile_rows[nmt] = (cnt - r < BM) ? (cnt - r) : BM;
                    nmt++;
                }
            }
            g_num_mt = nmt;
            for (int j = nmt; j < MAXMT; j++) { g_tile_rows[j] = 0; g_tile_e[j] = 0; g_tile_row0[j] = 0; }
        }
        return;
    }

    int i = (blockIdx.x - 1) * 1024 + threadIdx.x;   // vec8 index
    const void* src; __half* dst; int idx;
    if (i < NX8) { src = x; dst = g_xh; idx = i; }
    else if (i < NX8 + NW8) { src = w; dst = g_wh; idx = i - NX8; }
    else return;

    uint4 probe = reinterpret_cast<const uint4*>(x)[0];   // broadcast, cached
    bool isf32 = ((probe.x | probe.y | probe.z | probe.w) & 0x1FFFu) == 0u;

    if (isf32) {
        const float4* sf = reinterpret_cast<const float4*>(src);
        float4 a = sf[2 * idx], b = sf[2 * idx + 1];
        __half2 h0 = __floats2half2_rn(a.x, a.y);
        __half2 h1 = __floats2half2_rn(a.z, a.w);
        __half2 h2 = __floats2half2_rn(b.x, b.y);
        __half2 h3 = __floats2half2_rn(b.z, b.w);
        uint4 o;
        o.x = *reinterpret_cast<uint32_t*>(&h0);
        o.y = *reinterpret_cast<uint32_t*>(&h1);
        o.z = *reinterpret_cast<uint32_t*>(&h2);
        o.w = *reinterpret_cast<uint32_t*>(&h3);
        reinterpret_cast<uint4*>(dst)[idx] = o;
    } else {
        reinterpret_cast<uint4*>(dst)[idx] = reinterpret_cast<const uint4*>(src)[idx];
    }
}

// ============================ grouped GEMM =================================
// 256 threads = 8 warps, warp grid 2(M)x4(N), each warp 64x32, fp32 accum.
// 3-stage cp.async pipeline, 2 CTAs/SM. B-fragment double-buffer across k16
// steps (+8 regs, fits the 128-reg cap) so each step's MMAs wait only on A.
__global__ void __launch_bounds__(256, 2) moe_gemm(float* __restrict__ out) {
    extern __shared__ char smem[];
    const __half* __restrict__ x = g_xh;
    const __half* __restrict__ wts = g_wh;
    const int tid = threadIdx.x;
    const int lane = tid & 31;
    const int wid = tid >> 5;
    const int warp_m = wid & 1;   // 0..1
    const int warp_n = wid >> 1;  // 0..3

    const int mt = blockIdx.x >> 5;     // NT = 32
    const int nt = blockIdx.x & 31;
    if (mt >= g_num_mt) return;
    const int rows = g_tile_rows[mt];
    if (rows <= 0) return;
    const int e = g_tile_e[mt];
    const int row0 = g_tile_row0[mt];
    const int nb = nt * BN;

    const uint32_t sbase = smem_u32(smem);

    // ---- A cp.async setup: 128 rows x 8 segs(16B); thread does 4 (gathered) ----
    const int rA = tid >> 3;          // 0..31, +32*j
    const int segA = tid & 7;
    const __half* aptr[4];
    uint32_t adst[4];
#pragma unroll
    for (int j = 0; j < 4; j++) {
        int rowj = rA + 32 * j;
        int rr = (rowj < rows) ? rowj : 0;
        int tok = g_perm[row0 + rr];
        aptr[j] = x + (size_t)tok * CK + segA * 8;
        adst[j] = sbase + (uint32_t)rowj * A_PITCH + (uint32_t)segA * 16u;
    }
    // ---- B cp.async setup: 64 rows x 16 segs(16B); thread does 4, single base ----
    const int rB0 = tid >> 4;        // 0..15
    const int sB0 = tid & 15;
    const __half* bsrc = wts + ((size_t)e * CK + rB0) * CN + nb + sB0 * 8;
    const uint32_t bdst0 = sbase + A_BYTES + (uint32_t)rB0 * B_PITCH
                         + (uint32_t)((sB0 ^ (rB0 & 7)) * 16);

    // ---- pipeline ----
    auto load_stage = [&](int c2) {
        uint32_t soff = (uint32_t)(c2 % STAGES) * STAGE_BYTES;
        size_t ka = (size_t)c2 * BK;
        size_t kb = (size_t)c2 * BK * CN;
#pragma unroll
        for (int j = 0; j < 4; j++) cp16(adst[j] + soff, aptr[j] + ka);
#pragma unroll
        for (int j = 0; j < 4; j++)
            cp16(bdst0 + soff + (uint32_t)j * (16u * B_PITCH),
                 bsrc + kb + (size_t)j * 16 * CN);
        CP_COMMIT();
    };

#pragma unroll
    for (int c2 = 0; c2 < STAGES - 1; c2++) load_stage(c2);

    float acc[4][4][4];
#pragma unroll
    for (int i = 0; i < 4; i++)
#pragma unroll
        for (int j = 0; j < 4; j++)
#pragma unroll
            for (int q = 0; q < 4; q++) acc[i][j][q] = 0.0f;

    const uint32_t a_row_base = (uint32_t)(warp_m * 64 + (lane & 15));
    const uint32_t a_col16 = (uint32_t)(lane >> 4) * 16u;
    const uint32_t b_krow_lane = (uint32_t)(lane & 15);
    const uint32_t b_cseg_base = (uint32_t)(warp_n * 4 + (lane >> 4));

    // B-fragment loader for a given k16 within the stage at base bb
    auto load_bfrag = [&](uint32_t bb, int k16, uint32_t bf[2][4]) {
        uint32_t krow = (uint32_t)k16 * 16u + b_krow_lane;
#pragma unroll
        for (int p = 0; p < 2; p++) {
            uint32_t cseg = (b_cseg_base + p * 2) ^ (krow & 7u);
            ldsm_x4_t(bf[p], bb + krow * B_PITCH + cseg * 16u);
        }
    };

    for (int c2 = 0; c2 < NCH; c2++) {
        CP_WAIT(STAGES - 2);
        __syncthreads();
        // tail: always commit a group so wait_group forces completion.
        if (c2 + STAGES - 1 < NCH) load_stage(c2 + STAGES - 1);
        else                       CP_COMMIT();

        uint32_t ab = sbase + (uint32_t)(c2 % STAGES) * STAGE_BYTES;
        uint32_t bb = ab + A_BYTES;

        // prime B double-buffer for k16=0
        uint32_t bcur[2][4], bnxt[2][4];
        load_bfrag(bb, 0, bcur);

#pragma unroll
        for (int k16 = 0; k16 < BK / 16; k16++) {
            uint32_t a[4][4];
#pragma unroll
            for (int m = 0; m < 4; m++) {
                uint32_t row = a_row_base + m * 16;
                ldsm_x4(a[m], ab + row * A_PITCH + (uint32_t)k16 * 32u + a_col16);
            }
            if (k16 < BK / 16 - 1) load_bfrag(bb, k16 + 1, bnxt);
#pragma unroll
            for (int m = 0; m < 4; m++)
#pragma unroll
                for (int j = 0; j < 4; j++)
                    mma16816(acc[m][j], a[m], bcur[j >> 1][(j & 1) * 2],
                             bcur[j >> 1][(j & 1) * 2 + 1]);
#pragma unroll
            for (int p = 0; p < 2; p++)
#pragma unroll
                for (int q = 0; q < 4; q++) bcur[p][q] = bnxt[p][q];
        }
    }

    // ---- epilogue: fp32 accum -> fp16 rounding -> FLOAT32 stores ----
    const int rm_base = warp_m * 64 + (lane >> 2);
    const int cn_base = nb + warp_n * 32 + (lane & 3) * 2;
#pragma unroll
    for (int m = 0; m < 4; m++) {
        int rm0 = rm_base + m * 16;
        bool ok0 = rm0 < rows;
        bool ok1 = rm0 + 8 < rows;
        float* o0 = out + (size_t)(row0 + rm0) * CN;
        float* o1 = o0 + (size_t)8 * CN;
#pragma unroll
        for (int j = 0; j < 4; j++) {
            int cn = cn_base + (j >> 1) * 16 + (j & 1) * 8;
            if (ok0) {
                float2 v = make_float2(rnd16(acc[m][j][0]), rnd16(acc[m][j][1]));
                *reinterpret_cast<float2*>(o0 + cn) = v;
            }
            if (ok1) {
                float2 v = make_float2(rnd16(acc[m][j][2]), rnd16(acc[m][j][3]));
                *reinterpret_cast<float2*>(o1 + cn) = v;
            }
        }
    }
}

// ============================ launch =======================================
extern "C" void kernel_launch(void* const* d_in, const int* in_sizes, int n_in,
                              void* d_out, int out_size) {
    const void* x = nullptr;
    const int*  ei = nullptr;
    const void* w = nullptr;
    for (int i = 0; i < n_in; i++) {
        if (in_sizes[i] == CM * CK)            x  = d_in[i];
        else if (in_sizes[i] == CM)            ei = (const int*)d_in[i];
        else if (in_sizes[i] == CE * CK * CN)  w  = d_in[i];
    }
    float* out = (float*)d_out;

    // 2 launches/call: fused (sort + convert), gemm.
    fused_pre<<<PRE_BLOCKS, 1024>>>(ei, x, w);

    cudaFuncSetAttribute(moe_gemm, cudaFuncAttributeMaxDynamicSharedMemorySize, SMEM_TOTAL);
    moe_gemm<<<MAXMT * NT, 256, SMEM_TOTAL>>>(out);
}